// round 1
// baseline (speedup 1.0000x reference)
#include <cuda_runtime.h>
#include <math.h>

#define F 64
#define H 4
#define NCAP 10240
#define ECAP 163840

// ---------------- scratch (device globals; no allocation allowed) ----------
__device__ float g_rad[NCAP * H * F];   // radial projection  [n][h][f]
__device__ float g_tan[NCAP * H * F];   // tangential proj    [n][h][f]
__device__ float g_sr[NCAP * H];        // radial score per node/head
__device__ float g_st[NCAP * H];        // tangential score per node/head
__device__ float g_mr[NCAP * H];        // segment max (radial)
__device__ float g_mt[NCAP * H];        // segment max (tangential)
__device__ float g_dr[NCAP * H];        // segment denom (radial)
__device__ float g_dt[NCAP * H];        // segment denom (tangential)
__device__ float g_ar[ECAP * H];        // per-edge logits -> exp weights (radial)
__device__ float g_at[ECAP * H];        // per-edge logits -> exp weights (tangential)
__device__ float g_outpre[NCAP * F];    // head-averaged message accumulator
__device__ float g_vr[H * F];           // w_proj[h] @ radial_score[h]
__device__ float g_vt[H * F];           // w_proj[h] @ tangential_score[h]
__device__ float g_scale;               // softplus(radial_distance_log_scale)

__device__ __forceinline__ float softplus_f(float v) {
    return (v > 20.f) ? v : log1pf(expf(v));
}

// float atomic max via ordered integer bit tricks
__device__ __forceinline__ void atomicMaxF(float* addr, float v) {
    if (v >= 0.f) atomicMax((int*)addr, __float_as_int(v));
    else          atomicMin((unsigned int*)addr, (unsigned int)__float_as_int(v));
}

// ---------------- tiny prep: score vectors + scale ------------------------
__global__ void k_prep(const float* __restrict__ wproj,
                       const float* __restrict__ rscore,
                       const float* __restrict__ tscore,
                       const float* __restrict__ rdls) {
    int tid = threadIdx.x;              // 256 threads => (h,f)
    int h = tid >> 6, f = tid & 63;
    const float* wp = wproj + h * F * F + f * F;
    const float* rs = rscore + h * F;
    const float* ts = tscore + h * F;
    float ar = 0.f, at = 0.f;
#pragma unroll 8
    for (int g = 0; g < F; ++g) { float w = wp[g]; ar += w * rs[g]; at += w * ts[g]; }
    g_vr[tid] = ar; g_vt[tid] = at;
    if (tid == 0) g_scale = softplus_f(rdls[0]);
}

// ---------------- init accumulators ---------------------------------------
__global__ void k_init(int n) {
    int i = blockIdx.x * blockDim.x + threadIdx.x;
    if (i < n * H) {
        g_mr[i] = -INFINITY; g_mt[i] = -INFINITY;
        g_dr[i] = 0.f;       g_dt[i] = 0.f;
    }
    if (i < n * F) g_outpre[i] = 0.f;
}

// ---------------- per-head projections: rad/tan = x @ W[h] ----------------
__global__ void k_proj(const float* __restrict__ x,
                       const float* __restrict__ radW,
                       const float* __restrict__ tanW,
                       int n) {
    __shared__ float xs[64][65];
    __shared__ float ws[64 * 64];
    int hm = blockIdx.y;            // 0..7 : (head, matrix)
    int h = hm >> 1;
    int mat = hm & 1;
    int node0 = blockIdx.x * 64;
    const float* W = (mat ? tanW : radW) + h * F * F;
    int tid = threadIdx.x;
    for (int idx = tid; idx < 64 * 64; idx += 256) {
        int row = idx >> 6, col = idx & 63;
        int node = node0 + row;
        xs[row][col] = (node < n) ? x[node * F + col] : 0.f;
        ws[idx] = W[idx];
    }
    __syncthreads();
    int tx = tid & 15, ty = tid >> 4;
    int g0 = tx * 4, ny = ty * 4;
    float acc[4][4] = {};
#pragma unroll 16
    for (int f = 0; f < 64; ++f) {
        float4 w = *(const float4*)&ws[f * 64 + g0];
#pragma unroll
        for (int i = 0; i < 4; ++i) {
            float xv = xs[ny + i][f];
            acc[i][0] += xv * w.x; acc[i][1] += xv * w.y;
            acc[i][2] += xv * w.z; acc[i][3] += xv * w.w;
        }
    }
    float* dst = mat ? g_tan : g_rad;
#pragma unroll
    for (int i = 0; i < 4; ++i) {
        int node = node0 + ny + i;
        if (node < n)
            *(float4*)&dst[(node * H + h) * F + g0] =
                make_float4(acc[i][0], acc[i][1], acc[i][2], acc[i][3]);
    }
}

// ---------------- per-node attention scores -------------------------------
__global__ void k_scores(const float* __restrict__ x, int n) {
    __shared__ float vr[H * F], vt[H * F];
    for (int i = threadIdx.x; i < H * F; i += blockDim.x) { vr[i] = g_vr[i]; vt[i] = g_vt[i]; }
    __syncthreads();
    int node = blockIdx.x * blockDim.x + threadIdx.x;
    if (node >= n) return;
    float sr[4] = {0.f, 0.f, 0.f, 0.f};
    float st[4] = {0.f, 0.f, 0.f, 0.f};
    const float4* xp = (const float4*)(x + node * F);
#pragma unroll 4
    for (int q = 0; q < 16; ++q) {
        float4 xv = xp[q];
        int f = q * 4;
#pragma unroll
        for (int h = 0; h < 4; ++h) {
            sr[h] += xv.x * vr[h * F + f]     + xv.y * vr[h * F + f + 1]
                   + xv.z * vr[h * F + f + 2] + xv.w * vr[h * F + f + 3];
            st[h] += xv.x * vt[h * F + f]     + xv.y * vt[h * F + f + 1]
                   + xv.z * vt[h * F + f + 2] + xv.w * vt[h * F + f + 3];
        }
    }
    *(float4*)&g_sr[node * H] = make_float4(sr[0], sr[1], sr[2], sr[3]);
    *(float4*)&g_st[node * H] = make_float4(st[0], st[1], st[2], st[3]);
}

// ---------------- edge pass 1: logits + segment max -----------------------
__global__ void k_edge1(const int* __restrict__ ei,
                        const float* __restrict__ elen,
                        const float* __restrict__ tbias,
                        const float* __restrict__ twt,
                        int e) {
    int idx = blockIdx.x * blockDim.x + threadIdx.x;
    if (idx >= e) return;
    int s = ei[idx], r = ei[e + idx];
    float len = elen[idx];
    float sc = g_scale;
    float4 v;
    v = *(const float4*)&g_sr[s * H]; float srs[4] = {v.x, v.y, v.z, v.w};
    v = *(const float4*)&g_sr[r * H]; float srr[4] = {v.x, v.y, v.z, v.w};
    v = *(const float4*)&g_st[s * H]; float sts[4] = {v.x, v.y, v.z, v.w};
    v = *(const float4*)&g_st[r * H]; float str_[4] = {v.x, v.y, v.z, v.w};
    float lr[4], lt[4];
#pragma unroll
    for (int h = 0; h < 4; ++h) {
        float a = tbias[h] + twt[h] * len;
        float temp = softplus_f(a) + 1e-4f;
        lr[h] = ((srs[h] - srr[h]) - sc * len) / temp;
        lt[h] = sts[h] - str_[h];
        atomicMaxF(&g_mr[r * H + h], lr[h]);
        atomicMaxF(&g_mt[r * H + h], lt[h]);
    }
    *(float4*)&g_ar[idx * H] = make_float4(lr[0], lr[1], lr[2], lr[3]);
    *(float4*)&g_at[idx * H] = make_float4(lt[0], lt[1], lt[2], lt[3]);
}

// ---------------- edge pass 2: exp + segment denom -------------------------
__global__ void k_edge2(const int* __restrict__ ei, int e) {
    int idx = blockIdx.x * blockDim.x + threadIdx.x;
    if (idx >= e) return;
    int r = ei[e + idx];
    float4 lr = *(const float4*)&g_ar[idx * H];
    float4 lt = *(const float4*)&g_at[idx * H];
    float4 mr = *(const float4*)&g_mr[r * H];
    float4 mt = *(const float4*)&g_mt[r * H];
    float ar[4] = {__expf(lr.x - mr.x), __expf(lr.y - mr.y),
                   __expf(lr.z - mr.z), __expf(lr.w - mr.w)};
    float at[4] = {__expf(lt.x - mt.x), __expf(lt.y - mt.y),
                   __expf(lt.z - mt.z), __expf(lt.w - mt.w)};
#pragma unroll
    for (int h = 0; h < 4; ++h) {
        atomicAdd(&g_dr[r * H + h], ar[h]);
        atomicAdd(&g_dt[r * H + h], at[h]);
    }
    *(float4*)&g_ar[idx * H] = make_float4(ar[0], ar[1], ar[2], ar[3]);
    *(float4*)&g_at[idx * H] = make_float4(at[0], at[1], at[2], at[3]);
}

// ---------------- edge pass 3: alpha * sender features scatter ------------
// one warp per edge; lane handles f = 2*lane, 2*lane+1 (float2)
__global__ void k_edge3(const int* __restrict__ ei, int e) {
    int gid = blockIdx.x * blockDim.x + threadIdx.x;
    int we = gid >> 5;
    int lane = gid & 31;
    if (we >= e) return;
    int s = ei[we], r = ei[e + we];
    float4 a4 = *(const float4*)&g_ar[we * H];
    float4 d4 = *(const float4*)&g_dr[r * H];
    float arr[4] = {a4.x / d4.x, a4.y / d4.y, a4.z / d4.z, a4.w / d4.w};
    a4 = *(const float4*)&g_at[we * H];
    d4 = *(const float4*)&g_dt[r * H];
    float att[4] = {a4.x / d4.x, a4.y / d4.y, a4.z / d4.z, a4.w / d4.w};
    int f0 = lane * 2;
    const float* rp = &g_rad[(s * H) * F + f0];
    const float* tp = &g_tan[(s * H) * F + f0];
    float accx = 0.f, accy = 0.f;
#pragma unroll
    for (int h = 0; h < 4; ++h) {
        float2 rv = *(const float2*)(rp + h * F);
        float2 tv = *(const float2*)(tp + h * F);
        accx += arr[h] * rv.x + att[h] * tv.x;
        accy += arr[h] * rv.y + att[h] * tv.y;
    }
    accx *= 0.25f; accy *= 0.25f;
    atomicAdd(&g_outpre[r * F + f0],     accx);
    atomicAdd(&g_outpre[r * F + f0 + 1], accy);
}

// ---------------- epilogue: correction + @ w_out + residual ---------------
__global__ void k_final(const float* __restrict__ x,
                        const float* __restrict__ wout,
                        float* __restrict__ out, int n) {
    __shared__ float xs[64][65];
    __shared__ float ws[64 * 64];
    int node0 = blockIdx.x * 64;
    int tid = threadIdx.x;
    for (int idx = tid; idx < 64 * 64; idx += 256) {
        int row = idx >> 6, col = idx & 63;
        int node = node0 + row;
        float val = 0.f;
        if (node < n) {
            val = g_outpre[node * F + col];
            if (g_dr[node * H] > 0.f) {   // node has >=1 incoming edge
                float corr = 0.f;
#pragma unroll
                for (int h = 0; h < 4; ++h)
                    corr += g_rad[(node * H + h) * F + col]
                          + g_tan[(node * H + h) * F + col];
                val -= 0.25f * corr;
            }
        }
        xs[row][col] = val;
        ws[idx] = wout[idx];
    }
    __syncthreads();
    int tx = tid & 15, ty = tid >> 4;
    int g0 = tx * 4, ny = ty * 4;
    float acc[4][4] = {};
#pragma unroll 16
    for (int f = 0; f < 64; ++f) {
        float4 w = *(const float4*)&ws[f * 64 + g0];
#pragma unroll
        for (int i = 0; i < 4; ++i) {
            float xv = xs[ny + i][f];
            acc[i][0] += xv * w.x; acc[i][1] += xv * w.y;
            acc[i][2] += xv * w.z; acc[i][3] += xv * w.w;
        }
    }
#pragma unroll
    for (int i = 0; i < 4; ++i) {
        int node = node0 + ny + i;
        if (node < n) {
            float4 xv = *(const float4*)&x[node * F + g0];
            *(float4*)&out[node * F + g0] =
                make_float4(acc[i][0] + xv.x, acc[i][1] + xv.y,
                            acc[i][2] + xv.z, acc[i][3] + xv.w);
        }
    }
}

extern "C" void kernel_launch(void* const* d_in, const int* in_sizes, int n_in,
                              void* d_out, int out_size) {
    const float* x     = (const float*)d_in[0];
    const int*   ei    = (const int*)  d_in[1];
    /* d_in[2] = edge_vec (unused by the reference) */
    const float* elen  = (const float*)d_in[3];
    const float* wproj = (const float*)d_in[4];
    const float* radW  = (const float*)d_in[5];
    const float* tanW  = (const float*)d_in[6];
    const float* rsc   = (const float*)d_in[7];
    const float* tsc   = (const float*)d_in[8];
    const float* rdls  = (const float*)d_in[9];
    const float* tbias = (const float*)d_in[10];
    const float* twt   = (const float*)d_in[11];
    const float* wout  = (const float*)d_in[12];
    float* out = (float*)d_out;

    int n = in_sizes[0] / F;
    int e = in_sizes[3];

    k_prep<<<1, 256>>>(wproj, rsc, tsc, rdls);
    k_init<<<(n * F + 255) / 256, 256>>>(n);
    dim3 gp((n + 63) / 64, H * 2);
    k_proj<<<gp, 256>>>(x, radW, tanW, n);
    k_scores<<<(n + 127) / 128, 128>>>(x, n);
    k_edge1<<<(e + 255) / 256, 256>>>(ei, elen, tbias, twt, e);
    k_edge2<<<(e + 255) / 256, 256>>>(ei, e);
    k_edge3<<<(e * 32 + 255) / 256, 256>>>(ei, e);
    k_final<<<(n + 63) / 64, 256>>>(x, wout, out, n);
}

// round 2
// speedup vs baseline: 1.2332x; 1.2332x over previous
#include <cuda_runtime.h>
#include <cuda_fp16.h>
#include <math.h>

#define F 64
#define H 4
#define NCAP 10240
#define ECAP 163840

// ---------------- scratch (device globals; no allocation allowed) ----------
__device__ __half g_p[NCAP * 8 * F];   // projections [n][c][f], c=0..3 radial h, 4..7 tangential h
__device__ float  g_s[NCAP * 8];       // per-node scores: [n][rad h0..3, tan h0..3]
__device__ float  g_d[NCAP * 8];       // softmax denominators, same c layout
__device__ float  g_w[ECAP * 8];       // per-edge exp weights, same c layout
__device__ float  g_outpre[NCAP * F];  // head-averaged message accumulator
__device__ float  g_vr[H * F];         // w_proj[h] @ radial_score[h]
__device__ float  g_vt[H * F];         // w_proj[h] @ tangential_score[h]
__device__ float  g_scale;             // softplus(radial_distance_log_scale)

__device__ __forceinline__ float softplus_f(float v) {
    return (v > 20.f) ? v : log1pf(expf(v));
}

// ---------------- tiny prep: score vectors + scale ------------------------
__global__ void k_prep(const float* __restrict__ wproj,
                       const float* __restrict__ rscore,
                       const float* __restrict__ tscore,
                       const float* __restrict__ rdls) {
    int tid = threadIdx.x;              // 256 threads => (h,f)
    int h = tid >> 6;
    const float* wp = wproj + h * F * F + (tid & 63) * F;
    const float* rs = rscore + h * F;
    const float* ts = tscore + h * F;
    float ar = 0.f, at = 0.f;
#pragma unroll 8
    for (int g = 0; g < F; ++g) { float w = wp[g]; ar += w * rs[g]; at += w * ts[g]; }
    g_vr[tid] = ar; g_vt[tid] = at;
    if (tid == 0) g_scale = softplus_f(rdls[0]);
}

// ---------------- init accumulators ---------------------------------------
__global__ void k_init(int n) {
    int i = blockIdx.x * blockDim.x + threadIdx.x;
    if (i < n * 8) g_d[i] = 0.f;
    if (i < n * F) g_outpre[i] = 0.f;
}

// ---- per-head projections p = x @ W[c]  (+ scores in the c==0 tiles) ------
__global__ void k_proj(const float* __restrict__ x,
                       const float* __restrict__ radW,
                       const float* __restrict__ tanW,
                       int n) {
    __shared__ float xs[64][65];
    __shared__ float ws[64 * 64];
    __shared__ float vrs[H * F], vts[H * F];
    int c = blockIdx.y;             // 0..3 radial heads, 4..7 tangential heads
    int h = c & 3;
    int node0 = blockIdx.x * 64;
    const float* W = ((c >> 2) ? tanW : radW) + h * F * F;
    int tid = threadIdx.x;
    for (int idx = tid; idx < 64 * 64; idx += 256) {
        int row = idx >> 6, col = idx & 63;
        int node = node0 + row;
        xs[row][col] = (node < n) ? x[node * F + col] : 0.f;
        ws[idx] = W[idx];
    }
    if (c == 0) { vrs[tid] = g_vr[tid]; vts[tid] = g_vt[tid]; }
    __syncthreads();

    int tx = tid & 15, ty = tid >> 4;
    int g0 = tx * 4, ny = ty * 4;
    float acc[4][4] = {};
#pragma unroll 16
    for (int f = 0; f < 64; ++f) {
        float4 w = *(const float4*)&ws[f * 64 + g0];
#pragma unroll
        for (int i = 0; i < 4; ++i) {
            float xv = xs[ny + i][f];
            acc[i][0] += xv * w.x; acc[i][1] += xv * w.y;
            acc[i][2] += xv * w.z; acc[i][3] += xv * w.w;
        }
    }
#pragma unroll
    for (int i = 0; i < 4; ++i) {
        int node = node0 + ny + i;
        if (node < n) {
            __half2* dst = (__half2*)&g_p[((size_t)node * 8 + c) * F + g0];
            dst[0] = __floats2half2_rn(acc[i][0], acc[i][1]);
            dst[1] = __floats2half2_rn(acc[i][2], acc[i][3]);
        }
    }

    // per-node attention scores (only the c==0 tile column does this)
    if (c == 0) {
        int ln = tid >> 2, sh = tid & 3;
        int node = node0 + ln;
        if (node < n) {
            float sr = 0.f, st = 0.f;
#pragma unroll 16
            for (int f = 0; f < 64; ++f) {
                float xv = xs[ln][f];
                sr += xv * vrs[sh * F + f];
                st += xv * vts[sh * F + f];
            }
            g_s[node * 8 + sh]     = sr;
            g_s[node * 8 + 4 + sh] = st;
        }
    }
}

// -------- fused edge pass: logits -> exp weight -> denominator ------------
__global__ void k_edge12(const int* __restrict__ ei,
                         const float* __restrict__ elen,
                         const float* __restrict__ tbias,
                         const float* __restrict__ twt,
                         int e) {
    int idx = blockIdx.x * blockDim.x + threadIdx.x;
    if (idx >= e) return;
    int s = ei[idx], r = ei[e + idx];
    float len = elen[idx];
    float sc = g_scale;
    float4 ss0 = *(const float4*)&g_s[s * 8];
    float4 ss1 = *(const float4*)&g_s[s * 8 + 4];
    float4 rr0 = *(const float4*)&g_s[r * 8];
    float4 rr1 = *(const float4*)&g_s[r * 8 + 4];
    float dsr[4] = {ss0.x - rr0.x, ss0.y - rr0.y, ss0.z - rr0.z, ss0.w - rr0.w};
    float dst_[4] = {ss1.x - rr1.x, ss1.y - rr1.y, ss1.z - rr1.z, ss1.w - rr1.w};
    float wr[4], wt[4];
#pragma unroll
    for (int h = 0; h < 4; ++h) {
        float temp = softplus_f(tbias[h] + twt[h] * len) + 1e-4f;
        wr[h] = __expf((dsr[h] - sc * len) / temp);
        wt[h] = __expf(dst_[h]);
        atomicAdd(&g_d[r * 8 + h],     wr[h]);
        atomicAdd(&g_d[r * 8 + 4 + h], wt[h]);
    }
    *(float4*)&g_w[idx * 8]     = make_float4(wr[0], wr[1], wr[2], wr[3]);
    *(float4*)&g_w[idx * 8 + 4] = make_float4(wt[0], wt[1], wt[2], wt[3]);
}

// -------- edge scatter: alpha * sender projections -> outpre ---------------
// one warp per edge; lane handles f = 2*lane, 2*lane+1
__global__ void k_edge3(const int* __restrict__ ei, int e) {
    int gid = blockIdx.x * blockDim.x + threadIdx.x;
    int we = gid >> 5;
    int lane = gid & 31;
    if (we >= e) return;
    int s = ei[we], r = ei[e + we];
    float4 w0 = *(const float4*)&g_w[we * 8];
    float4 w1 = *(const float4*)&g_w[we * 8 + 4];
    float4 d0 = *(const float4*)&g_d[r * 8];
    float4 d1 = *(const float4*)&g_d[r * 8 + 4];
    float a[8];
    a[0] = __fdividef(w0.x, d0.x); a[1] = __fdividef(w0.y, d0.y);
    a[2] = __fdividef(w0.z, d0.z); a[3] = __fdividef(w0.w, d0.w);
    a[4] = __fdividef(w1.x, d1.x); a[5] = __fdividef(w1.y, d1.y);
    a[6] = __fdividef(w1.z, d1.z); a[7] = __fdividef(w1.w, d1.w);
    int f0 = lane * 2;
    const __half2* pp = (const __half2*)&g_p[(size_t)s * 8 * F + f0];
    float accx = 0.f, accy = 0.f;
#pragma unroll
    for (int c = 0; c < 8; ++c) {
        float2 v = __half22float2(pp[c * (F / 2)]);
        accx += a[c] * v.x;
        accy += a[c] * v.y;
    }
    atomicAdd(&g_outpre[r * F + f0],     accx * 0.25f);
    atomicAdd(&g_outpre[r * F + f0 + 1], accy * 0.25f);
}

// ---------------- epilogue: correction + @ w_out + residual ---------------
__global__ void k_final(const float* __restrict__ x,
                        const float* __restrict__ wout,
                        float* __restrict__ out, int n) {
    __shared__ float xs[64][65];
    __shared__ float ws[64 * 64];
    int node0 = blockIdx.x * 64;
    int tid = threadIdx.x;
    for (int idx = tid; idx < 64 * 64; idx += 256) {
        int row = idx >> 6, col = idx & 63;
        int node = node0 + row;
        float val = 0.f;
        if (node < n) {
            val = g_outpre[node * F + col];
            if (g_d[node * 8] > 0.f) {   // node has >=1 incoming edge
                float corr = 0.f;
#pragma unroll
                for (int c = 0; c < 8; ++c)
                    corr += __half2float(g_p[((size_t)node * 8 + c) * F + col]);
                val -= 0.25f * corr;
            }
        }
        xs[row][col] = val;
        ws[idx] = wout[idx];
    }
    __syncthreads();
    int tx = tid & 15, ty = tid >> 4;
    int g0 = tx * 4, ny = ty * 4;
    float acc[4][4] = {};
#pragma unroll 16
    for (int f = 0; f < 64; ++f) {
        float4 w = *(const float4*)&ws[f * 64 + g0];
#pragma unroll
        for (int i = 0; i < 4; ++i) {
            float xv = xs[ny + i][f];
            acc[i][0] += xv * w.x; acc[i][1] += xv * w.y;
            acc[i][2] += xv * w.z; acc[i][3] += xv * w.w;
        }
    }
#pragma unroll
    for (int i = 0; i < 4; ++i) {
        int node = node0 + ny + i;
        if (node < n) {
            float4 xv = *(const float4*)&x[node * F + g0];
            *(float4*)&out[node * F + g0] =
                make_float4(acc[i][0] + xv.x, acc[i][1] + xv.y,
                            acc[i][2] + xv.z, acc[i][3] + xv.w);
        }
    }
}

extern "C" void kernel_launch(void* const* d_in, const int* in_sizes, int n_in,
                              void* d_out, int out_size) {
    const float* x     = (const float*)d_in[0];
    const int*   ei    = (const int*)  d_in[1];
    /* d_in[2] = edge_vec (unused by the reference) */
    const float* elen  = (const float*)d_in[3];
    const float* wproj = (const float*)d_in[4];
    const float* radW  = (const float*)d_in[5];
    const float* tanW  = (const float*)d_in[6];
    const float* rsc   = (const float*)d_in[7];
    const float* tsc   = (const float*)d_in[8];
    const float* rdls  = (const float*)d_in[9];
    const float* tbias = (const float*)d_in[10];
    const float* twt   = (const float*)d_in[11];
    const float* wout  = (const float*)d_in[12];
    float* out = (float*)d_out;

    int n = in_sizes[0] / F;
    int e = in_sizes[3];

    k_prep<<<1, 256>>>(wproj, rsc, tsc, rdls);
    k_init<<<(n * F + 255) / 256, 256>>>(n);
    dim3 gp((n + 63) / 64, 8);
    k_proj<<<gp, 256>>>(x, radW, tanW, n);
    k_edge12<<<(e + 255) / 256, 256>>>(ei, elen, tbias, twt, e);
    k_edge3<<<(e * 32 + 255) / 256, 256>>>(ei, e);
    k_final<<<(n + 63) / 64, 256>>>(x, wout, out, n);
}